// round 10
// baseline (speedup 1.0000x reference)
#include <cuda_runtime.h>
#include <math.h>

#define N_NODES 100000
#define N_EDGES 3200000
#define D_IN    128
#define D_HID   16
#define D_OUT   2

// ---------------- constant weights ----------------
__constant__ float cW1[D_IN * D_HID];
__constant__ float cW2[D_HID * D_OUT];
__constant__ float cb1[D_HID];
__constant__ float cb2[D_OUT];

// ---------------- scratch ----------------
__device__ int   g_deg [N_NODES];
__device__ float g_dinv[N_NODES];
__device__ float g_h1  [N_NODES * D_HID];   // (x @ W1) * dinv
__device__ float g_agg1[N_NODES * D_HID];   // fp32 edge accumulator
__device__ float g_g2  [N_NODES * D_OUT];   // (h2 @ W2) * dinv
__device__ float g_agg2[N_NODES * D_OUT];

// ---------------- init: zero accumulators, deg=1 (self loop) ----------------
__global__ void zero_kernel() {
    int i = blockIdx.x * blockDim.x + threadIdx.x;
    if (i < N_NODES * D_HID) g_agg1[i] = 0.0f;
    if (i < N_NODES * D_OUT) g_agg2[i] = 0.0f;
    if (i < N_NODES)         g_deg[i]  = 1;
}

// ---------------- degree ----------------
__global__ void deg_kernel(const int* __restrict__ ei) {
    int e = blockIdx.x * blockDim.x + threadIdx.x;
    if (e >= N_EDGES) return;
    atomicAdd(&g_deg[ei[N_EDGES + e]], 1);
}

__global__ void dinv_kernel() {
    int i = blockIdx.x * blockDim.x + threadIdx.x;
    if (i < N_NODES) g_dinv[i] = rsqrtf((float)g_deg[i]);
}

// ---------------- GEMM1: h1 = (x @ W1) * dinv, 4 threads per node ----------------
__global__ void __launch_bounds__(256) gemm1_kernel(const float* __restrict__ x) {
    int gt = blockIdx.x * 256 + threadIdx.x;
    int node = gt >> 2;
    int q    = gt & 3;
    if (node >= N_NODES) return;
    const float4* xr = (const float4*)(x + (size_t)node * D_IN);

    float acc[D_HID];
#pragma unroll
    for (int j = 0; j < D_HID; j++) acc[j] = 0.0f;

#pragma unroll 8
    for (int i = 0; i < 8; i++) {            // 8 float4 per thread
        int k4 = q * 8 + i;
        float4 xv = xr[k4];
        float xs[4] = {xv.x, xv.y, xv.z, xv.w};
#pragma unroll
        for (int kk = 0; kk < 4; kk++) {
            const float* w = &cW1[(k4 * 4 + kk) * D_HID];
#pragma unroll
            for (int j = 0; j < D_HID; j++)
                acc[j] = fmaf(xs[kk], w[j], acc[j]);
        }
    }
    // combine 4 partial threads (xor 1, xor 2)
#pragma unroll
    for (int j = 0; j < D_HID; j++)
        acc[j] += __shfl_xor_sync(0xFFFFFFFF, acc[j], 1);
#pragma unroll
    for (int j = 0; j < D_HID; j++)
        acc[j] += __shfl_xor_sync(0xFFFFFFFF, acc[j], 2);

    const float di = g_dinv[node];
    float4 o = make_float4(acc[q * 4 + 0] * di, acc[q * 4 + 1] * di,
                           acc[q * 4 + 2] * di, acc[q * 4 + 3] * di);
    *(float4*)&g_h1[(size_t)node * D_HID + q * 4] = o;
}

// ---------------- vector reductions ----------------
__device__ __forceinline__ void red_v4(float* p, float4 v) {
    asm volatile("red.global.add.v4.f32 [%0], {%1,%2,%3,%4};"
                 :: "l"(p), "f"(v.x), "f"(v.y), "f"(v.z), "f"(v.w) : "memory");
}
__device__ __forceinline__ void red_v2(float* p, float a, float b) {
    asm volatile("red.global.add.v2.f32 [%0], {%1,%2};"
                 :: "l"(p), "f"(a), "f"(b) : "memory");
}

// ---------------- layer-1 aggregation: 2 edges per thread ----------------
__global__ void agg1_kernel(const int* __restrict__ ei) {
    int t  = blockIdx.x * blockDim.x + threadIdx.x;
    int e0 = t * 2;
    if (e0 >= N_EDGES) return;
    int2 s2 = *(const int2*)&ei[e0];
    int2 d2 = *(const int2*)&ei[N_EDGES + e0];

    const float4* ha = (const float4*)&g_h1[(size_t)s2.x * D_HID];
    const float4* hb = (const float4*)&g_h1[(size_t)s2.y * D_HID];
    float4 a0 = ha[0], a1 = ha[1], a2 = ha[2], a3 = ha[3];
    float4 b0 = hb[0], b1 = hb[1], b2 = hb[2], b3 = hb[3];

    float* oa = &g_agg1[(size_t)d2.x * D_HID];
    float* ob = &g_agg1[(size_t)d2.y * D_HID];
    red_v4(oa +  0, a0); red_v4(ob +  0, b0);
    red_v4(oa +  4, a1); red_v4(ob +  4, b1);
    red_v4(oa +  8, a2); red_v4(ob +  8, b2);
    red_v4(oa + 12, a3); red_v4(ob + 12, b3);
}

// ------- fused: h2 = relu(dinv*(agg1 + h1) + b1); g2 = (h2 @ W2)*dinv -------
__global__ void project_kernel() {
    int i = blockIdx.x * blockDim.x + threadIdx.x;
    if (i >= N_NODES) return;
    float di = g_dinv[i];
    const float4* a4 = (const float4*)&g_agg1[(size_t)i * D_HID];
    const float4* h4 = (const float4*)&g_h1[(size_t)i * D_HID];
    float z0 = 0.f, z1 = 0.f;
#pragma unroll
    for (int j4 = 0; j4 < 4; j4++) {
        float4 a = a4[j4];
        float4 h = h4[j4];
        float hv[4] = {a.x + h.x, a.y + h.y, a.z + h.z, a.w + h.w};
#pragma unroll
        for (int k = 0; k < 4; k++) {
            int j = j4 * 4 + k;
            float h2 = fmaxf(fmaf(di, hv[k], cb1[j]), 0.f);
            z0 = fmaf(h2, cW2[j * D_OUT + 0], z0);
            z1 = fmaf(h2, cW2[j * D_OUT + 1], z1);
        }
    }
    g_g2[i * 2 + 0] = z0 * di;
    g_g2[i * 2 + 1] = z1 * di;
}

// ---------------- layer-2 aggregation: 2 edges per thread ----------------
__global__ void agg2_kernel(const int* __restrict__ ei) {
    int t  = blockIdx.x * blockDim.x + threadIdx.x;
    int e0 = t * 2;
    if (e0 >= N_EDGES) return;
    int2 s2 = *(const int2*)&ei[e0];
    int2 d2 = *(const int2*)&ei[N_EDGES + e0];
    float2 ma = *(const float2*)&g_g2[s2.x * 2];
    float2 mb = *(const float2*)&g_g2[s2.y * 2];
    red_v2(&g_agg2[d2.x * 2], ma.x, ma.y);
    red_v2(&g_agg2[d2.y * 2], mb.x, mb.y);
}

// ---------------- final: post-scale, bias, log_softmax ----------------
__global__ void final_kernel(float* __restrict__ out) {
    int i = blockIdx.x * blockDim.x + threadIdx.x;
    if (i >= N_NODES) return;
    float di = g_dinv[i];
    float z0 = fmaf(di, g_agg2[i * 2 + 0] + g_g2[i * 2 + 0], cb2[0]);
    float z1 = fmaf(di, g_agg2[i * 2 + 1] + g_g2[i * 2 + 1], cb2[1]);
    float m  = fmaxf(z0, z1);
    float lse = m + logf(expf(z0 - m) + expf(z1 - m));
    out[i * 2 + 0] = z0 - lse;
    out[i * 2 + 1] = z1 - lse;
}

// ---------------- launch ----------------
extern "C" void kernel_launch(void* const* d_in, const int* in_sizes, int n_in,
                              void* d_out, int out_size) {
    const float* x  = (const float*)d_in[0];
    const float* W1 = (const float*)d_in[1];
    const float* b1 = (const float*)d_in[2];
    const float* W2 = (const float*)d_in[3];
    const float* b2 = (const float*)d_in[4];
    const int*   ei = (const int*)d_in[5];
    float* out = (float*)d_out;

    cudaMemcpyToSymbolAsync(cW1, W1, D_IN * D_HID * sizeof(float), 0, cudaMemcpyDeviceToDevice);
    cudaMemcpyToSymbolAsync(cW2, W2, D_HID * D_OUT * sizeof(float), 0, cudaMemcpyDeviceToDevice);
    cudaMemcpyToSymbolAsync(cb1, b1, D_HID * sizeof(float), 0, cudaMemcpyDeviceToDevice);
    cudaMemcpyToSymbolAsync(cb2, b2, D_OUT * sizeof(float), 0, cudaMemcpyDeviceToDevice);

    const int T = 256;
    zero_kernel<<<(N_NODES * D_HID + T - 1) / T, T>>>();
    deg_kernel<<<(N_EDGES + T - 1) / T, T>>>(ei);
    dinv_kernel<<<(N_NODES + T - 1) / T, T>>>();
    gemm1_kernel<<<(N_NODES * 4 + 255) / 256, 256>>>(x);
    agg1_kernel<<<(N_EDGES / 2 + T - 1) / T, T>>>(ei);
    project_kernel<<<(N_NODES + T - 1) / T, T>>>();
    agg2_kernel<<<(N_EDGES / 2 + T - 1) / T, T>>>(ei);
    final_kernel<<<(N_NODES + T - 1) / T, T>>>(out);
}

// round 11
// speedup vs baseline: 2.4740x; 2.4740x over previous
#include <cuda_runtime.h>
#include <math.h>

#define N_NODES 100000
#define N_EDGES 3200000
#define D_IN    128
#define D_HID   16
#define D_OUT   2

// ---------------- constant weights ----------------
__constant__ float cW1[D_IN * D_HID];
__constant__ float cW2[D_HID * D_OUT];
__constant__ float cb1[D_HID];
__constant__ float cb2[D_OUT];

// ---------------- scratch ----------------
__device__ int   g_deg [N_NODES];           // zeroed via memset; deg = count+1
__device__ float g_dinv[N_NODES];
__device__ float g_h1  [N_NODES * D_HID];   // (x @ W1) * dinv
__device__ float g_agg1[N_NODES * D_HID];   // zeroed inside gemm1
__device__ float g_g2  [N_NODES * D_OUT];   // (h2 @ W2) * dinv
__device__ float g_agg2[N_NODES * D_OUT];   // zeroed via memset

// ---------------- degree (histogram; self loop added in dinv) ----------------
__global__ void deg_kernel(const int* __restrict__ ei) {
    int e = blockIdx.x * blockDim.x + threadIdx.x;
    if (e >= N_EDGES) return;
    atomicAdd(&g_deg[ei[N_EDGES + e]], 1);
}

__global__ void dinv_kernel() {
    int i = blockIdx.x * blockDim.x + threadIdx.x;
    if (i < N_NODES) g_dinv[i] = rsqrtf((float)(g_deg[i] + 1));
}

// ---------------- GEMM1: h1 = (x @ W1) * dinv, one thread per node ----------------
// W1 in constant memory: all lanes read the SAME address every step (broadcast).
// Also zeroes this node's g_agg1 row (replaces a separate zero kernel).
__global__ void __launch_bounds__(256) gemm1_kernel(const float* __restrict__ x) {
    const int node = blockIdx.x * 256 + threadIdx.x;
    if (node >= N_NODES) return;
    const float4* xr = (const float4*)(x + (size_t)node * D_IN);

    float acc[D_HID];
#pragma unroll
    for (int j = 0; j < D_HID; j++) acc[j] = 0.0f;

#pragma unroll 8
    for (int k4 = 0; k4 < D_IN / 4; k4++) {
        float4 xv = xr[k4];
        float xs[4] = {xv.x, xv.y, xv.z, xv.w};
#pragma unroll
        for (int kk = 0; kk < 4; kk++) {
            const float* w = &cW1[(k4 * 4 + kk) * D_HID];
#pragma unroll
            for (int j = 0; j < D_HID; j++)
                acc[j] = fmaf(xs[kk], w[j], acc[j]);
        }
    }

    const float di = g_dinv[node];
    float4* out = (float4*)&g_h1[(size_t)node * D_HID];
    float4* az  = (float4*)&g_agg1[(size_t)node * D_HID];
    const float4 z4 = make_float4(0.f, 0.f, 0.f, 0.f);
#pragma unroll
    for (int j4 = 0; j4 < 4; j4++) {
        out[j4] = make_float4(acc[j4 * 4 + 0] * di, acc[j4 * 4 + 1] * di,
                              acc[j4 * 4 + 2] * di, acc[j4 * 4 + 3] * di);
        az[j4]  = z4;
    }
}

// ---------------- vector reductions ----------------
__device__ __forceinline__ void red_v4(float* p, float4 v) {
    asm volatile("red.global.add.v4.f32 [%0], {%1,%2,%3,%4};"
                 :: "l"(p), "f"(v.x), "f"(v.y), "f"(v.z), "f"(v.w) : "memory");
}
__device__ __forceinline__ void red_v2(float* p, float a, float b) {
    asm volatile("red.global.add.v2.f32 [%0], {%1,%2};"
                 :: "l"(p), "f"(a), "f"(b) : "memory");
}

// ---------------- layer-1 aggregation: one thread per edge ----------------
__global__ void agg1_kernel(const int* __restrict__ ei) {
    int e = blockIdx.x * blockDim.x + threadIdx.x;
    if (e >= N_EDGES) return;
    int s = ei[e];
    int d = ei[N_EDGES + e];
    const float4* h = (const float4*)&g_h1[(size_t)s * D_HID];
    float* out = &g_agg1[(size_t)d * D_HID];
    float4 v0 = h[0], v1 = h[1], v2 = h[2], v3 = h[3];
    red_v4(out +  0, v0);
    red_v4(out +  4, v1);
    red_v4(out +  8, v2);
    red_v4(out + 12, v3);
}

// ------- fused: h2 = relu(dinv*(agg1 + h1) + b1); g2 = (h2 @ W2)*dinv -------
__global__ void project_kernel() {
    int i = blockIdx.x * blockDim.x + threadIdx.x;
    if (i >= N_NODES) return;
    float di = g_dinv[i];
    const float4* a4 = (const float4*)&g_agg1[(size_t)i * D_HID];
    const float4* h4 = (const float4*)&g_h1[(size_t)i * D_HID];
    float z0 = 0.f, z1 = 0.f;
#pragma unroll
    for (int j4 = 0; j4 < 4; j4++) {
        float4 a = a4[j4];
        float4 h = h4[j4];
        float hv[4] = {a.x + h.x, a.y + h.y, a.z + h.z, a.w + h.w};
#pragma unroll
        for (int k = 0; k < 4; k++) {
            int j = j4 * 4 + k;
            float h2 = fmaxf(fmaf(di, hv[k], cb1[j]), 0.f);
            z0 = fmaf(h2, cW2[j * D_OUT + 0], z0);
            z1 = fmaf(h2, cW2[j * D_OUT + 1], z1);
        }
    }
    g_g2[i * 2 + 0] = z0 * di;
    g_g2[i * 2 + 1] = z1 * di;
}

// ---------------- layer-2 aggregation: one thread per edge ----------------
__global__ void agg2_kernel(const int* __restrict__ ei) {
    int e = blockIdx.x * blockDim.x + threadIdx.x;
    if (e >= N_EDGES) return;
    int s = ei[e];
    int d = ei[N_EDGES + e];
    float2 m = *(const float2*)&g_g2[s * 2];
    red_v2(&g_agg2[d * 2], m.x, m.y);
}

// ---------------- final: post-scale, bias, log_softmax ----------------
__global__ void final_kernel(float* __restrict__ out) {
    int i = blockIdx.x * blockDim.x + threadIdx.x;
    if (i >= N_NODES) return;
    float di = g_dinv[i];
    float z0 = fmaf(di, g_agg2[i * 2 + 0] + g_g2[i * 2 + 0], cb2[0]);
    float z1 = fmaf(di, g_agg2[i * 2 + 1] + g_g2[i * 2 + 1], cb2[1]);
    float m  = fmaxf(z0, z1);
    float lse = m + logf(expf(z0 - m) + expf(z1 - m));
    out[i * 2 + 0] = z0 - lse;
    out[i * 2 + 1] = z1 - lse;
}

// ---------------- launch ----------------
extern "C" void kernel_launch(void* const* d_in, const int* in_sizes, int n_in,
                              void* d_out, int out_size) {
    const float* x  = (const float*)d_in[0];
    const float* W1 = (const float*)d_in[1];
    const float* b1 = (const float*)d_in[2];
    const float* W2 = (const float*)d_in[3];
    const float* b2 = (const float*)d_in[4];
    const int*   ei = (const int*)d_in[5];
    float* out = (float*)d_out;

    cudaMemcpyToSymbolAsync(cW1, W1, D_IN * D_HID * sizeof(float), 0, cudaMemcpyDeviceToDevice);
    cudaMemcpyToSymbolAsync(cW2, W2, D_HID * D_OUT * sizeof(float), 0, cudaMemcpyDeviceToDevice);
    cudaMemcpyToSymbolAsync(cb1, b1, D_HID * sizeof(float), 0, cudaMemcpyDeviceToDevice);
    cudaMemcpyToSymbolAsync(cb2, b2, D_OUT * sizeof(float), 0, cudaMemcpyDeviceToDevice);

    void* p_deg  = nullptr;
    void* p_agg2 = nullptr;
    cudaGetSymbolAddress(&p_deg,  g_deg);
    cudaGetSymbolAddress(&p_agg2, g_agg2);
    cudaMemsetAsync(p_deg,  0, N_NODES * sizeof(int));
    cudaMemsetAsync(p_agg2, 0, N_NODES * D_OUT * sizeof(float));

    const int T = 256;
    deg_kernel<<<(N_EDGES + T - 1) / T, T>>>(ei);
    dinv_kernel<<<(N_NODES + T - 1) / T, T>>>();
    gemm1_kernel<<<(N_NODES + 255) / 256, 256>>>(x);
    agg1_kernel<<<(N_EDGES + T - 1) / T, T>>>(ei);
    project_kernel<<<(N_NODES + T - 1) / T, T>>>();
    agg2_kernel<<<(N_EDGES + T - 1) / T, T>>>(ei);
    final_kernel<<<(N_NODES + T - 1) / T, T>>>(out);
}

// round 12
// speedup vs baseline: 3.1918x; 1.2901x over previous
#include <cuda_runtime.h>
#include <math.h>

#define N_NODES 100000
#define N_EDGES 3200000
#define D_IN    128
#define D_HID   16
#define D_OUT   2

// ---------------- constant weights ----------------
__constant__ float cW1[D_IN * D_HID];
__constant__ float cW2[D_HID * D_OUT];
__constant__ float cb1[D_HID];
__constant__ float cb2[D_OUT];

// ---------------- scratch ----------------
__device__ int   g_deg [N_NODES];           // zeroed via memset; deg = count+1
__device__ float g_dinv[N_NODES];
__device__ float g_h1  [N_NODES * D_HID];   // (x @ W1) * dinv
__device__ float g_agg1[N_NODES * D_HID];   // zeroed inside gemm1
__device__ float g_g2  [N_NODES * D_OUT];   // (h2 @ W2) * dinv
__device__ float g_agg2[N_NODES * D_OUT];   // zeroed via memset

// ---------------- degree (histogram; self loop added in dinv) ----------------
__global__ void deg_kernel(const int* __restrict__ ei) {
    int e = blockIdx.x * blockDim.x + threadIdx.x;
    if (e >= N_EDGES) return;
    atomicAdd(&g_deg[ei[N_EDGES + e]], 1);
}

__global__ void dinv_kernel() {
    int i = blockIdx.x * blockDim.x + threadIdx.x;
    if (i < N_NODES) g_dinv[i] = rsqrtf((float)(g_deg[i] + 1));
}

// ---------------- GEMM1: h1 = (x @ W1) * dinv, one thread per node ----------------
// W1 in constant memory (warp-uniform -> broadcast). Also zeroes g_agg1 row.
__global__ void __launch_bounds__(256) gemm1_kernel(const float* __restrict__ x) {
    const int node = blockIdx.x * 256 + threadIdx.x;
    if (node >= N_NODES) return;
    const float4* xr = (const float4*)(x + (size_t)node * D_IN);

    float acc[D_HID];
#pragma unroll
    for (int j = 0; j < D_HID; j++) acc[j] = 0.0f;

#pragma unroll 8
    for (int k4 = 0; k4 < D_IN / 4; k4++) {
        float4 xv = xr[k4];
        float xs[4] = {xv.x, xv.y, xv.z, xv.w};
#pragma unroll
        for (int kk = 0; kk < 4; kk++) {
            const float* w = &cW1[(k4 * 4 + kk) * D_HID];
#pragma unroll
            for (int j = 0; j < D_HID; j++)
                acc[j] = fmaf(xs[kk], w[j], acc[j]);
        }
    }

    const float di = g_dinv[node];
    float4* out = (float4*)&g_h1[(size_t)node * D_HID];
    float4* az  = (float4*)&g_agg1[(size_t)node * D_HID];
    const float4 z4 = make_float4(0.f, 0.f, 0.f, 0.f);
#pragma unroll
    for (int j4 = 0; j4 < 4; j4++) {
        out[j4] = make_float4(acc[j4 * 4 + 0] * di, acc[j4 * 4 + 1] * di,
                              acc[j4 * 4 + 2] * di, acc[j4 * 4 + 3] * di);
        az[j4]  = z4;
    }
}

// ---------------- vector reductions ----------------
__device__ __forceinline__ void red_v4(float* p, float4 v) {
    asm volatile("red.global.add.v4.f32 [%0], {%1,%2,%3,%4};"
                 :: "l"(p), "f"(v.x), "f"(v.y), "f"(v.z), "f"(v.w) : "memory");
}
__device__ __forceinline__ void red_v2(float* p, float a, float b) {
    asm volatile("red.global.add.v2.f32 [%0], {%1,%2};"
                 :: "l"(p), "f"(a), "f"(b) : "memory");
}

// ----- layer-1 aggregation: 4 lanes per edge (coalesced 64B gather + RED) -----
// 8 edges per warp. Lane l: edge = warpbase + (l>>2), feature quad = l&3.
// Gather: the 4 lanes of an edge read one consecutive 64B row (1 line vs 4
// scattered lines per edge before). RED: 4 consecutive 16B quads per edge.
__global__ void __launch_bounds__(256) agg1_kernel(const int* __restrict__ ei) {
    int gt   = blockIdx.x * 256 + threadIdx.x;
    int e    = gt >> 2;                 // edge id (N_EDGES divisible by 8 -> no partial warps)
    int sub  = gt & 3;                  // feature quad
    if (e >= N_EDGES) return;
    int s = ei[e];                      // 4-lane redundant, sector-broadcast
    int d = ei[N_EDGES + e];
    float4 v = *(const float4*)&g_h1[(size_t)s * D_HID + sub * 4];
    red_v4(&g_agg1[(size_t)d * D_HID + sub * 4], v);
}

// ------- fused: h2 = relu(dinv*(agg1 + h1) + b1); g2 = (h2 @ W2)*dinv -------
__global__ void project_kernel() {
    int i = blockIdx.x * blockDim.x + threadIdx.x;
    if (i >= N_NODES) return;
    float di = g_dinv[i];
    const float4* a4 = (const float4*)&g_agg1[(size_t)i * D_HID];
    const float4* h4 = (const float4*)&g_h1[(size_t)i * D_HID];
    float z0 = 0.f, z1 = 0.f;
#pragma unroll
    for (int j4 = 0; j4 < 4; j4++) {
        float4 a = a4[j4];
        float4 h = h4[j4];
        float hv[4] = {a.x + h.x, a.y + h.y, a.z + h.z, a.w + h.w};
#pragma unroll
        for (int k = 0; k < 4; k++) {
            int j = j4 * 4 + k;
            float h2 = fmaxf(fmaf(di, hv[k], cb1[j]), 0.f);
            z0 = fmaf(h2, cW2[j * D_OUT + 0], z0);
            z1 = fmaf(h2, cW2[j * D_OUT + 1], z1);
        }
    }
    g_g2[i * 2 + 0] = z0 * di;
    g_g2[i * 2 + 1] = z1 * di;
}

// ---------------- layer-2 aggregation: one thread per edge ----------------
__global__ void agg2_kernel(const int* __restrict__ ei) {
    int e = blockIdx.x * blockDim.x + threadIdx.x;
    if (e >= N_EDGES) return;
    int s = ei[e];
    int d = ei[N_EDGES + e];
    float2 m = *(const float2*)&g_g2[s * 2];
    red_v2(&g_agg2[d * 2], m.x, m.y);
}

// ---------------- final: post-scale, bias, log_softmax ----------------
__global__ void final_kernel(float* __restrict__ out) {
    int i = blockIdx.x * blockDim.x + threadIdx.x;
    if (i >= N_NODES) return;
    float di = g_dinv[i];
    float z0 = fmaf(di, g_agg2[i * 2 + 0] + g_g2[i * 2 + 0], cb2[0]);
    float z1 = fmaf(di, g_agg2[i * 2 + 1] + g_g2[i * 2 + 1], cb2[1]);
    float m  = fmaxf(z0, z1);
    float lse = m + logf(expf(z0 - m) + expf(z1 - m));
    out[i * 2 + 0] = z0 - lse;
    out[i * 2 + 1] = z1 - lse;
}

// ---------------- launch ----------------
extern "C" void kernel_launch(void* const* d_in, const int* in_sizes, int n_in,
                              void* d_out, int out_size) {
    const float* x  = (const float*)d_in[0];
    const float* W1 = (const float*)d_in[1];
    const float* b1 = (const float*)d_in[2];
    const float* W2 = (const float*)d_in[3];
    const float* b2 = (const float*)d_in[4];
    const int*   ei = (const int*)d_in[5];
    float* out = (float*)d_out;

    cudaMemcpyToSymbolAsync(cW1, W1, D_IN * D_HID * sizeof(float), 0, cudaMemcpyDeviceToDevice);
    cudaMemcpyToSymbolAsync(cW2, W2, D_HID * D_OUT * sizeof(float), 0, cudaMemcpyDeviceToDevice);
    cudaMemcpyToSymbolAsync(cb1, b1, D_HID * sizeof(float), 0, cudaMemcpyDeviceToDevice);
    cudaMemcpyToSymbolAsync(cb2, b2, D_OUT * sizeof(float), 0, cudaMemcpyDeviceToDevice);

    void* p_deg  = nullptr;
    void* p_agg2 = nullptr;
    cudaGetSymbolAddress(&p_deg,  g_deg);
    cudaGetSymbolAddress(&p_agg2, g_agg2);
    cudaMemsetAsync(p_deg,  0, N_NODES * sizeof(int));
    cudaMemsetAsync(p_agg2, 0, N_NODES * D_OUT * sizeof(float));

    const int T = 256;
    deg_kernel<<<(N_EDGES + T - 1) / T, T>>>(ei);
    dinv_kernel<<<(N_NODES + T - 1) / T, T>>>();
    gemm1_kernel<<<(N_NODES + 255) / 256, 256>>>(x);
    agg1_kernel<<<(N_EDGES * 4 + 255) / 256, 256>>>(ei);
    project_kernel<<<(N_NODES + T - 1) / T, T>>>();
    agg2_kernel<<<(N_EDGES + T - 1) / T, T>>>(ei);
    final_kernel<<<(N_NODES + T - 1) / T, T>>>(out);
}